// round 5
// baseline (speedup 1.0000x reference)
#include <cuda_runtime.h>
#include <cstdint>

// Per-row top-k masking (keep k largest/smallest along last axis, zero the rest).
// One warp per row of C=768 floats. x is staged in SMEM (lane-private slots) so
// only the 6 packed top-byte words live in registers -> high occupancy.
// Phase 1: SWAR byte-pack + 8-step binary search (dp4a counts, REDUX).
// Phase 2: scan-based candidate compaction from SMEM.
// Phase 3: rank-select: bitonic (m<=32), nibble-stage on register candidates
//          (m<=128), smem bit-loop (m<=256), full smem bit-loop (m>256).
// Phase 4: threshold pass reading x back from SMEM.

#define FULL_MASK 0xFFFFFFFFu

constexpr int C_DIM = 768;
constexpr int V4    = 6;     // float4 elements per lane
constexpr int WARPS = 8;     // rows per block
constexpr int CAP   = 256;   // candidate slots per warp

__device__ __forceinline__ unsigned f2ord(unsigned b) {
    return b ^ (unsigned)(((int)b >> 31) | 0x80000000);
}
__device__ __forceinline__ unsigned ord2f(unsigned u) {
    return u ^ (unsigned)(0x80000000u | ~((unsigned)((int)u >> 31)));
}

// Sort <=32 values across the warp, return the r-th largest (1-based).
__device__ __forceinline__ unsigned warp_rank_select(const unsigned* cand,
                                                     int m, int r, int lane)
{
    unsigned v = (lane < m) ? cand[lane] : 0u;
    #pragma unroll
    for (int size = 2; size <= 32; size <<= 1) {
        #pragma unroll
        for (int stride = size >> 1; stride > 0; stride >>= 1) {
            unsigned o = __shfl_xor_sync(FULL_MASK, v, stride);
            bool tm = (((lane & stride) != 0) ^ ((lane & size) != 0));
            unsigned mx = v > o ? v : o;
            unsigned mn = v > o ? o : v;
            v = tm ? mx : mn;
        }
    }
    return __shfl_sync(FULL_MASK, v, 32 - r);
}

__global__ __launch_bounds__(WARPS * 32, 6)
void topk_mask_kernel(const float* __restrict__ x,
                      const int* __restrict__ kptr,
                      const int* __restrict__ lptr,
                      float* __restrict__ out,
                      int nrows)
{
    __shared__ float4   s_x[WARPS][C_DIM / 4];   // 24 KB: staged input
    __shared__ unsigned s_cand[WARPS][CAP];      //  8 KB: candidates

    const int warp = threadIdx.x >> 5;
    const int lane = threadIdx.x & 31;
    const int row  = blockIdx.x * WARPS + warp;
    if (row >= nrows) return;

    const int k       = *kptr;
    const int largest = *lptr;
    const unsigned flip = largest ? 0u : 0xFFFFFFFFu;

    const float4* __restrict__ xin =
        reinterpret_cast<const float4*>(x + (size_t)row * C_DIM);
    float4* __restrict__ xout =
        reinterpret_cast<float4*>(out + (size_t)row * C_DIM);

    const unsigned H  = 0x80808080u;
    const unsigned NH = 0x7F7F7F7Fu;
    const unsigned HX = H ^ flip;

    // ---- load, stash to smem (lane-private), pack ordered top-bytes ----
    unsigned p[V4], xm[V4];
    #pragma unroll
    for (int j = 0; j < V4; j++) {
        float4 v = xin[lane + 32 * j];
        s_x[warp][lane + 32 * j] = v;
        unsigned p01 = __byte_perm(__float_as_uint(v.x), __float_as_uint(v.y), 0x0073);
        unsigned p23 = __byte_perm(__float_as_uint(v.z), __float_as_uint(v.w), 0x0073);
        unsigned pk  = __byte_perm(p01, p23, 0x5410);
        unsigned s   = pk & H;
        unsigned mm  = (s >> 7) * 0x7Fu;
        p[j]  = pk ^ mm ^ HX;
        xm[j] = p[j] & NH;
    }

    // ---- 8-step binary search on the top byte ----
    unsigned lo = 0, hi = 256;
    int flo = C_DIM, fhi = 0;
    #pragma unroll
    for (int it = 0; it < 8; it++) {
        unsigned mid  = (lo + hi) >> 1;              // in [1,255]
        unsigned crep = (256u - mid) * 0x01010101u;
        unsigned cqm  = crep & NH;
        unsigned acc  = 0;
        #pragma unroll
        for (int j = 0; j < V4; j++) {
            unsigned s = xm[j] + cqm;                          // carry into bit7
            unsigned g = (p[j] & crep) | ((p[j] ^ crep) & s);  // one LOP3
            acc = __dp4a(g & H, 0x01010101u, acc);             // += 0x80 per match
        }
        int cnt = __reduce_add_sync(FULL_MASK, (int)acc) >> 7;
        if (cnt >= k) { lo = mid; flo = cnt; }
        else          { hi = mid; fhi = cnt; }
    }
    const unsigned d = lo;
    int r = k - fhi;           // rank inside the d-bin (1-based)
    int m = flo - fhi;         // bin population

    // ---- per-byte equality masks + scan; emit candidates from smem ----
    const unsigned drep = d * 0x01010101u;
    const unsigned dr7  = drep & NH;
    unsigned ym[V4];
    int ci = 0;
    #pragma unroll
    for (int j = 0; j < V4; j++) {
        unsigned z = p[j] ^ drep;
        unsigned a = (xm[j] ^ dr7) + NH;         // no cross-byte carry
        unsigned y = ~(a | z) & H;               // 0x80 per byte equal to d
        ym[j] = y;
        ci += __popc(y);
    }
    int sc = ci;
    #pragma unroll
    for (int sh = 1; sh < 32; sh <<= 1) {
        int t = __shfl_up_sync(FULL_MASK, sc, sh);
        if (lane >= sh) sc += t;
    }
    unsigned* cand = s_cand[warp];
    if (m <= CAP) {
        int pos = sc - ci;                       // exclusive prefix
        #pragma unroll
        for (int j = 0; j < V4; j++) {
            if (ym[j]) {
                float4 v = s_x[warp][lane + 32 * j];   // own slot: no sync needed
                unsigned w[4] = { __float_as_uint(v.x), __float_as_uint(v.y),
                                  __float_as_uint(v.z), __float_as_uint(v.w) };
                #pragma unroll
                for (int b = 0; b < 4; b++) {
                    if (ym[j] & (0x80u << (8*b)))
                        cand[pos++] = f2ord(w[b]) ^ flip;
                }
            }
        }
    }
    __syncwarp();

    // ---- rank-select the r-th largest among the m candidates ----
    unsigned cur = d << 24;
    unsigned thr_ord;

    if (m <= 32) {
        thr_ord = warp_rank_select(cand, m, r, lane);
    } else if (m <= 128) {
        // register-held candidates; 4-iter nibble stages until m<=32
        unsigned v[4];
        bool val[4];
        {
            const int W = (m + 31) >> 5;
            #pragma unroll
            for (int j = 0; j < 4; j++) {
                int idx = lane + 32 * j;
                val[j] = (j < W) && (idx < m);
                v[j] = val[j] ? cand[idx] : 0u;
            }
        }
        int bse = 0;
        int lev = 5;                              // nibble levels: bits 23-20 .. 3-0
        while (m > 32 && lev >= 0) {
            const int sh = lev * 4;
            int cb[4];
            #pragma unroll
            for (int j = 0; j < 4; j++)
                cb[j] = val[j] ? (int)((v[j] >> sh) & 0xFu) : -1;
            unsigned lo2 = 0, hi2 = 16;
            int flo2 = m, fhi2 = 0;
            #pragma unroll
            for (int it = 0; it < 4; it++) {
                int mid = (int)((lo2 + hi2) >> 1);
                int c = 0;
                #pragma unroll
                for (int j = 0; j < 4; j++) c += (cb[j] >= mid) ? 1 : 0;
                c = __reduce_add_sync(FULL_MASK, c);
                if (c >= r) { lo2 = mid; flo2 = c; }
                else        { hi2 = mid; fhi2 = c; }
            }
            const int d2 = (int)lo2;
            const int m2 = flo2 - fhi2;
            r  -= fhi2;
            cur |= ((unsigned)d2) << sh;
            // compact survivors into the other half (both halves < CAP)
            int fl[4]; int c2 = 0;
            #pragma unroll
            for (int j = 0; j < 4; j++) { fl[j] = (cb[j] == d2) ? 1 : 0; c2 += fl[j]; }
            int s2 = c2;
            #pragma unroll
            for (int shf = 1; shf < 32; shf <<= 1) {
                int t = __shfl_up_sync(FULL_MASK, s2, shf);
                if (lane >= shf) s2 += t;
            }
            int pos = ((bse == 0) ? 128 : 0) + (s2 - c2);
            #pragma unroll
            for (int j = 0; j < 4; j++) {
                if (fl[j]) cand[pos++] = v[j];
            }
            __syncwarp();
            bse = (bse == 0) ? 128 : 0;
            m = m2; lev--;
            if (m > 32) {
                const int W2 = (m + 31) >> 5;
                #pragma unroll
                for (int j = 0; j < 4; j++) {
                    int idx = lane + 32 * j;
                    val[j] = (j < W2) && (idx < m);
                    v[j] = val[j] ? cand[bse + idx] : 0u;
                }
            }
        }
        if (m <= 32) thr_ord = warp_rank_select(cand + bse, m, r, lane);
        else         thr_ord = cur;              // all bits fixed: remaining equal
    } else if (m <= CAP) {
        // heavy bin: exact strided bit-loop over smem candidates
        const bool valid0 = (lane < m);
        const unsigned v0 = valid0 ? cand[lane] : 0u;
        #pragma unroll 1
        for (int b = 23; b >= 0; b--) {
            int cl = (valid0 && (((v0 ^ cur) >> b) == 1u)) ? 1 : 0;
            for (int j = 32 + lane; j < m; j += 32)
                cl += (((cand[j] ^ cur) >> b) == 1u) ? 1 : 0;
            int c = __reduce_add_sync(FULL_MASK, cl);
            if (c >= r) cur |= (1u << b);
            else        r -= c;
        }
        thr_ord = cur;
    } else {
        // pathological bin (> CAP): exact bit-loop over smem-staged x
        #pragma unroll 1
        for (int b = 23; b >= 0; b--) {
            int cl = 0;
            #pragma unroll
            for (int j = 0; j < V4; j++) {
                float4 v = s_x[warp][lane + 32 * j];
                unsigned w[4] = { __float_as_uint(v.x), __float_as_uint(v.y),
                                  __float_as_uint(v.z), __float_as_uint(v.w) };
                #pragma unroll
                for (int b4 = 0; b4 < 4; b4++) {
                    unsigned uu = f2ord(w[b4]) ^ flip;
                    cl += (((uu ^ cur) >> b) == 1u) ? 1 : 0;
                }
            }
            int c = __reduce_add_sync(FULL_MASK, cl);
            if (c >= r) cur |= (1u << b);
            else        r -= c;
        }
        thr_ord = cur;
    }

    // ---- threshold pass: read x back from smem, write output ----
    if (largest) {
        const float thr = __uint_as_float(ord2f(thr_ord));
        #pragma unroll
        for (int i = 0; i < V4; i++) {
            float4 v = s_x[warp][lane + 32 * i];
            float4 o;
            o.x = (v.x >= thr) ? v.x : 0.0f;
            o.y = (v.y >= thr) ? v.y : 0.0f;
            o.z = (v.z >= thr) ? v.z : 0.0f;
            o.w = (v.w >= thr) ? v.w : 0.0f;
            xout[lane + 32 * i] = o;
        }
    } else {
        const float thr = __uint_as_float(ord2f(thr_ord ^ flip));
        #pragma unroll
        for (int i = 0; i < V4; i++) {
            float4 v = s_x[warp][lane + 32 * i];
            float4 o;
            o.x = (v.x <= thr) ? v.x : 0.0f;
            o.y = (v.y <= thr) ? v.y : 0.0f;
            o.z = (v.z <= thr) ? v.z : 0.0f;
            o.w = (v.w <= thr) ? v.w : 0.0f;
            xout[lane + 32 * i] = o;
        }
    }
}

extern "C" void kernel_launch(void* const* d_in, const int* in_sizes, int n_in,
                              void* d_out, int out_size)
{
    const float* x    = (const float*)d_in[0];
    const int*   kptr = (const int*)d_in[1];
    const int*   lptr = (const int*)d_in[2];
    float* out = (float*)d_out;

    int nrows = in_sizes[0] / C_DIM;
    int blocks = (nrows + WARPS - 1) / WARPS;
    topk_mask_kernel<<<blocks, WARPS * 32>>>(x, kptr, lptr, out, nrows);
}

// round 6
// speedup vs baseline: 1.0566x; 1.0566x over previous
#include <cuda_runtime.h>
#include <cstdint>

// Per-row exact top-k masking (keep k largest/smallest along last axis, zero rest).
// One warp per row of C=768 floats, all data register-resident, NO shared memory.
// The k-th value's 32 bits are found by up to four masked byte-plane searches:
//   level L: binary-search byte L of the rank-r element among "active" bytes
//   (active = matched all previously decided bytes), via SWAR 7-bit compares
//   (3 instr/word) + dp4a popcounts + REDUX. Common path exits after 2 levels
//   with a unique survivor extracted by equality mask + REDUX.MAX.

#define FULL_MASK 0xFFFFFFFFu

constexpr int C_DIM = 768;
constexpr int V4    = 6;     // float4 loads per lane (24 values/lane)
constexpr int WARPS = 8;     // rows per block

__device__ __forceinline__ unsigned f2ord(unsigned b) {
    return b ^ (unsigned)(((int)b >> 31) | 0x80000000);
}
__device__ __forceinline__ unsigned ord2f(unsigned u) {
    return u ^ (unsigned)(0x80000000u | ~((unsigned)((int)u >> 31)));
}

// Binary-search the byte value of the rank-r (descending, 1-based) element among
// active bytes. pl: packed byte plane; plm = pl & 0x7F7F7F7F; msk: 0x80 per
// active byte. In/out: r (becomes rank within returned bin), m (active count ->
// bin count). Returns the byte value d.
__device__ __forceinline__ int search_plane(const unsigned* pl, const unsigned* plm,
                                            const unsigned* msk, int& r, int& m)
{
    const unsigned REP1 = 0x01010101u;
    unsigned acc = 0;
    #pragma unroll
    for (int j = 0; j < V4; j++) acc = __dp4a(pl[j] & msk[j], REP1, acc);
    const int n1 = (int)(__reduce_add_sync(FULL_MASK, acc) >> 7);   // active with bit7

    int lo = 0, hi = 128, flo, fhi, base;
    if (n1 >= r) {   // threshold byte has bit7 set: count = (s & pl & msk)
        base = 128; flo = n1; fhi = 0;
        #pragma unroll 1
        for (int it = 0; it < 7; it++) {
            int mid = (lo + hi) >> 1;
            unsigned crep = (unsigned)(128 - mid) * REP1;
            unsigned a2 = 0;
            #pragma unroll
            for (int j = 0; j < V4; j++) {
                unsigned s = plm[j] + crep;            // bit7 <=> low7 >= mid
                a2 = __dp4a(s & pl[j] & msk[j], REP1, a2);
            }
            int cnt = (int)(__reduce_add_sync(FULL_MASK, a2) >> 7);
            if (cnt >= r) { lo = mid; flo = cnt; } else { hi = mid; fhi = cnt; }
        }
    } else {         // threshold byte has bit7 clear: count = ((s | pl) & msk)
        base = 0; flo = m; fhi = n1;
        #pragma unroll 1
        for (int it = 0; it < 7; it++) {
            int mid = (lo + hi) >> 1;
            unsigned crep = (unsigned)(128 - mid) * REP1;
            unsigned a2 = 0;
            #pragma unroll
            for (int j = 0; j < V4; j++) {
                unsigned s = plm[j] + crep;
                a2 = __dp4a((s | pl[j]) & msk[j], REP1, a2);
            }
            int cnt = (int)(__reduce_add_sync(FULL_MASK, a2) >> 7);
            if (cnt >= r) { lo = mid; flo = cnt; } else { hi = mid; fhi = cnt; }
        }
    }
    r -= fhi;
    m  = flo - fhi;
    return base + lo;
}

// Restrict msk to bytes of plane pl equal to d (exact zero-byte detect).
__device__ __forceinline__ void refine_mask(unsigned* msk, const unsigned* pl,
                                            const unsigned* plm, int d)
{
    const unsigned NH = 0x7F7F7F7Fu;
    const unsigned drep = (unsigned)d * 0x01010101u;
    const unsigned dr7  = drep & NH;
    #pragma unroll
    for (int j = 0; j < V4; j++) {
        unsigned z = pl[j] ^ drep;               // 0 byte <=> equal
        unsigned a = (plm[j] ^ dr7) + NH;        // bit7 set <=> low7(z) != 0
        msk[j] = ~a & ~z & msk[j];               // one LOP3 (msk is 0x80-only)
    }
}

// Exactly one active byte remains: return its full ordered value (warp-wide).
__device__ __forceinline__ unsigned extract_unique(const unsigned* msk,
                                                   const float* f, unsigned flip)
{
    unsigned best = 0;
    #pragma unroll
    for (int j = 0; j < V4; j++) {
        unsigned y = msk[j];
        if (y) {
            #pragma unroll
            for (int b = 0; b < 4; b++)
                if (y & (0x80u << (8*b)))
                    best = f2ord(__float_as_uint(f[4*j+b])) ^ flip;
        }
    }
    return __reduce_max_sync(FULL_MASK, best);
}

__global__ __launch_bounds__(WARPS * 32)
void topk_mask_kernel(const float* __restrict__ x,
                      const int* __restrict__ kptr,
                      const int* __restrict__ lptr,
                      float* __restrict__ out,
                      int nrows)
{
    const int warp = threadIdx.x >> 5;
    const int lane = threadIdx.x & 31;
    const int row  = blockIdx.x * WARPS + warp;
    if (row >= nrows) return;

    const int k       = *kptr;
    const int largest = *lptr;
    const unsigned flip = largest ? 0u : 0xFFFFFFFFu;

    const float4* __restrict__ xin =
        reinterpret_cast<const float4*>(x + (size_t)row * C_DIM);
    float4* __restrict__ xout =
        reinterpret_cast<float4*>(out + (size_t)row * C_DIM);

    const unsigned H  = 0x80808080u;
    const unsigned NH = 0x7F7F7F7Fu;
    const unsigned HX = H ^ flip;

    // ---- load x; pack ordered top-byte plane p ----
    float f[V4 * 4];
    unsigned p[V4], pm[V4], msk[V4];
    #pragma unroll
    for (int j = 0; j < V4; j++) {
        float4 v = xin[lane + 32 * j];
        f[4*j+0] = v.x; f[4*j+1] = v.y; f[4*j+2] = v.z; f[4*j+3] = v.w;
        unsigned p01 = __byte_perm(__float_as_uint(v.x), __float_as_uint(v.y), 0x0073);
        unsigned p23 = __byte_perm(__float_as_uint(v.z), __float_as_uint(v.w), 0x0073);
        unsigned pk  = __byte_perm(p01, p23, 0x5410);
        unsigned s   = pk & H;
        unsigned mm  = (s >> 7) * 0x7Fu;   // ordered-byte transform for negatives
        p[j]  = pk ^ mm ^ HX;
        pm[j] = p[j] & NH;
        msk[j] = H;                        // all active
    }

    // ---- level 1: top byte ----
    int r = k, m = C_DIM;
    int d = search_plane(p, pm, msk, r, m);
    unsigned cur = (unsigned)d << 24;
    refine_mask(msk, p, pm, d);

    unsigned thr_ord;
    bool resolved = false;

    if (m > 1) {
        // ---- pack byte-2 plane q (ordered): q = raw_byte2 ^ negmask ^ flip ----
        unsigned q[V4], qm[V4];
        #pragma unroll
        for (int j = 0; j < V4; j++) {
            unsigned t1 = ~(p[j] ^ flip) & H;          // 0x80 per negative float
            unsigned nm = (t1 >> 7) * 0xFFu;           // 0xFF per negative
            unsigned q01 = __byte_perm(__float_as_uint(f[4*j+0]),
                                       __float_as_uint(f[4*j+1]), 0x0062);
            unsigned q23 = __byte_perm(__float_as_uint(f[4*j+2]),
                                       __float_as_uint(f[4*j+3]), 0x0062);
            unsigned qraw = __byte_perm(q01, q23, 0x5410);
            q[j]  = qraw ^ nm ^ flip;
            qm[j] = q[j] & NH;
        }
        // ---- level 2: byte 2, masked by top-byte equality ----
        int d2 = search_plane(q, qm, msk, r, m);
        cur |= (unsigned)d2 << 16;
        refine_mask(msk, q, qm, d2);

        if (m > 1) {
            // ---- rare: top-16-bit collision. Convert f->ordered bits in place,
            //      run byte levels 3 and 4 the same way. ----
            #pragma unroll
            for (int i = 0; i < V4 * 4; i++)
                f[i] = __uint_as_float(f2ord(__float_as_uint(f[i])) ^ flip);

            unsigned r3[V4], r3m[V4];
            #pragma unroll
            for (int j = 0; j < V4; j++) {
                unsigned a01 = __byte_perm(__float_as_uint(f[4*j+0]),
                                           __float_as_uint(f[4*j+1]), 0x0051);
                unsigned a23 = __byte_perm(__float_as_uint(f[4*j+2]),
                                           __float_as_uint(f[4*j+3]), 0x0051);
                r3[j]  = __byte_perm(a01, a23, 0x5410);   // byte1 plane (ordered)
                r3m[j] = r3[j] & NH;
            }
            int d3 = search_plane(r3, r3m, msk, r, m);
            cur |= (unsigned)d3 << 8;
            refine_mask(msk, r3, r3m, d3);

            #pragma unroll
            for (int j = 0; j < V4; j++) {
                unsigned a01 = __byte_perm(__float_as_uint(f[4*j+0]),
                                           __float_as_uint(f[4*j+1]), 0x0040);
                unsigned a23 = __byte_perm(__float_as_uint(f[4*j+2]),
                                           __float_as_uint(f[4*j+3]), 0x0040);
                r3[j]  = __byte_perm(a01, a23, 0x5410);   // byte0 plane (ordered)
                r3m[j] = r3[j] & NH;
            }
            int d4 = search_plane(r3, r3m, msk, r, m);
            cur |= (unsigned)d4;
            thr_ord = cur;            // full 32 bits decided (duplicates exact)
            resolved = true;

            // restore f to raw floats
            #pragma unroll
            for (int i = 0; i < V4 * 4; i++)
                f[i] = __uint_as_float(ord2f(__float_as_uint(f[i]) ^ flip) );
        }
    }
    if (!resolved) {
        thr_ord = extract_unique(msk, f, flip);   // unique survivor's full value
    }

    // ---- threshold pass in float domain ----
    if (largest) {
        const float thr = __uint_as_float(ord2f(thr_ord));
        #pragma unroll
        for (int i = 0; i < V4; i++) {
            float4 o;
            o.x = (f[4*i+0] >= thr) ? f[4*i+0] : 0.0f;
            o.y = (f[4*i+1] >= thr) ? f[4*i+1] : 0.0f;
            o.z = (f[4*i+2] >= thr) ? f[4*i+2] : 0.0f;
            o.w = (f[4*i+3] >= thr) ? f[4*i+3] : 0.0f;
            xout[lane + 32 * i] = o;
        }
    } else {
        const float thr = __uint_as_float(ord2f(thr_ord ^ flip));
        #pragma unroll
        for (int i = 0; i < V4; i++) {
            float4 o;
            o.x = (f[4*i+0] <= thr) ? f[4*i+0] : 0.0f;
            o.y = (f[4*i+1] <= thr) ? f[4*i+1] : 0.0f;
            o.z = (f[4*i+2] <= thr) ? f[4*i+2] : 0.0f;
            o.w = (f[4*i+3] <= thr) ? f[4*i+3] : 0.0f;
            xout[lane + 32 * i] = o;
        }
    }
}

extern "C" void kernel_launch(void* const* d_in, const int* in_sizes, int n_in,
                              void* d_out, int out_size)
{
    const float* x    = (const float*)d_in[0];
    const int*   kptr = (const int*)d_in[1];
    const int*   lptr = (const int*)d_in[2];
    float* out = (float*)d_out;

    int nrows = in_sizes[0] / C_DIM;
    int blocks = (nrows + WARPS - 1) / WARPS;
    topk_mask_kernel<<<blocks, WARPS * 32>>>(x, kptr, lptr, out, nrows);
}

// round 7
// speedup vs baseline: 1.1916x; 1.1277x over previous
#include <cuda_runtime.h>
#include <cstdint>

// Per-row exact top-k masking (keep k largest/smallest along last axis, zero rest).
// One warp per row of C=768 floats, all data register-resident, NO shared memory.
// The k-th value's 32 bits are found by up to four masked byte-plane searches;
// byte planes for levels >=2 are built IN PLACE over the level-1 plane registers
// to keep true register demand ~55; __launch_bounds__(.,4) caps at 64 regs so
// 4 CTAs/SM are resident (latency hiding for the serial REDUX chains).

#define FULL_MASK 0xFFFFFFFFu

constexpr int C_DIM = 768;
constexpr int V4    = 6;     // float4 loads per lane (24 values/lane)
constexpr int WARPS = 8;     // rows per block

__device__ __forceinline__ unsigned f2ord(unsigned b) {
    return b ^ (unsigned)(((int)b >> 31) | 0x80000000);
}
__device__ __forceinline__ unsigned ord2f(unsigned u) {
    return u ^ (unsigned)(0x80000000u | ~((unsigned)((int)u >> 31)));
}

// Binary-search the byte value of the rank-r (descending, 1-based) element among
// active bytes. pl: packed byte plane; plm = pl & 0x7F7F7F7F; msk: 0x80 per
// active byte. In/out: r (rank within returned bin), m (active -> bin count).
__device__ __forceinline__ int search_plane(const unsigned* pl, const unsigned* plm,
                                            const unsigned* msk, int& r, int& m)
{
    const unsigned REP1 = 0x01010101u;
    unsigned acc = 0;
    #pragma unroll
    for (int j = 0; j < V4; j++) acc = __dp4a(pl[j] & msk[j], REP1, acc);
    const int n1 = (int)(__reduce_add_sync(FULL_MASK, acc) >> 7);   // active w/ bit7

    int lo = 0, hi = 128, flo, fhi, base;
    if (n1 >= r) {   // threshold byte has bit7 set: count = (s & pl & msk)
        base = 128; flo = n1; fhi = 0;
        #pragma unroll 1
        for (int it = 0; it < 7; it++) {
            int mid = (lo + hi) >> 1;
            unsigned crep = (unsigned)(128 - mid) * REP1;
            unsigned a2 = 0;
            #pragma unroll
            for (int j = 0; j < V4; j++) {
                unsigned s = plm[j] + crep;            // bit7 <=> low7 >= mid
                a2 = __dp4a(s & pl[j] & msk[j], REP1, a2);
            }
            int cnt = (int)(__reduce_add_sync(FULL_MASK, a2) >> 7);
            if (cnt >= r) { lo = mid; flo = cnt; } else { hi = mid; fhi = cnt; }
        }
    } else {         // threshold byte has bit7 clear: count = ((s | pl) & msk)
        base = 0; flo = m; fhi = n1;
        #pragma unroll 1
        for (int it = 0; it < 7; it++) {
            int mid = (lo + hi) >> 1;
            unsigned crep = (unsigned)(128 - mid) * REP1;
            unsigned a2 = 0;
            #pragma unroll
            for (int j = 0; j < V4; j++) {
                unsigned s = plm[j] + crep;
                a2 = __dp4a((s | pl[j]) & msk[j], REP1, a2);
            }
            int cnt = (int)(__reduce_add_sync(FULL_MASK, a2) >> 7);
            if (cnt >= r) { lo = mid; flo = cnt; } else { hi = mid; fhi = cnt; }
        }
    }
    r -= fhi;
    m  = flo - fhi;
    return base + lo;
}

// Restrict msk to bytes of plane pl equal to d (exact zero-byte detect).
__device__ __forceinline__ void refine_mask(unsigned* msk, const unsigned* pl,
                                            const unsigned* plm, int d)
{
    const unsigned NH = 0x7F7F7F7Fu;
    const unsigned drep = (unsigned)d * 0x01010101u;
    const unsigned dr7  = drep & NH;
    #pragma unroll
    for (int j = 0; j < V4; j++) {
        unsigned z = pl[j] ^ drep;               // 0 byte <=> equal
        unsigned a = (plm[j] ^ dr7) + NH;        // bit7 <=> low7(z) != 0
        msk[j] = ~a & ~z & msk[j];               // one LOP3 (msk is 0x80-only)
    }
}

// Exactly one active byte remains: return its full ordered value (warp-wide).
__device__ __forceinline__ unsigned extract_unique(const unsigned* msk,
                                                   const float* f, unsigned flip)
{
    unsigned best = 0;
    #pragma unroll
    for (int j = 0; j < V4; j++) {
        unsigned y = msk[j];
        if (y) {
            #pragma unroll
            for (int b = 0; b < 4; b++)
                if (y & (0x80u << (8*b)))
                    best = f2ord(__float_as_uint(f[4*j+b])) ^ flip;
        }
    }
    return __reduce_max_sync(FULL_MASK, best);
}

__global__ __launch_bounds__(WARPS * 32, 4)
void topk_mask_kernel(const float* __restrict__ x,
                      const int* __restrict__ kptr,
                      const int* __restrict__ lptr,
                      float* __restrict__ out,
                      int nrows)
{
    const int warp = threadIdx.x >> 5;
    const int lane = threadIdx.x & 31;
    const int row  = blockIdx.x * WARPS + warp;
    if (row >= nrows) return;

    const int k       = *kptr;
    const int largest = *lptr;
    const unsigned flip = largest ? 0u : 0xFFFFFFFFu;

    const float4* __restrict__ xin =
        reinterpret_cast<const float4*>(x + (size_t)row * C_DIM);
    float4* __restrict__ xout =
        reinterpret_cast<float4*>(out + (size_t)row * C_DIM);

    const unsigned H  = 0x80808080u;
    const unsigned NH = 0x7F7F7F7Fu;
    const unsigned HX = H ^ flip;

    // ---- load x; pack ordered top-byte plane into p/pm ----
    float f[V4 * 4];
    unsigned p[V4], pm[V4], msk[V4];
    #pragma unroll
    for (int j = 0; j < V4; j++) {
        float4 v = xin[lane + 32 * j];
        f[4*j+0] = v.x; f[4*j+1] = v.y; f[4*j+2] = v.z; f[4*j+3] = v.w;
        unsigned p01 = __byte_perm(__float_as_uint(v.x), __float_as_uint(v.y), 0x0073);
        unsigned p23 = __byte_perm(__float_as_uint(v.z), __float_as_uint(v.w), 0x0073);
        unsigned pk  = __byte_perm(p01, p23, 0x5410);
        unsigned s   = pk & H;
        unsigned mm  = (s >> 7) * 0x7Fu;   // ordered-byte transform for negatives
        p[j]  = pk ^ mm ^ HX;
        pm[j] = p[j] & NH;
        msk[j] = H;                        // all active
    }

    // ---- level 1: top byte ----
    int r = k, m = C_DIM;
    int d = search_plane(p, pm, msk, r, m);
    unsigned cur = (unsigned)d << 24;
    refine_mask(msk, p, pm, d);

    unsigned thr_ord;
    bool resolved = false;

    if (m > 1) {
        // ---- level 2 plane (byte 2, ordered) built IN PLACE over p/pm ----
        #pragma unroll
        for (int j = 0; j < V4; j++) {
            unsigned t1 = ~(p[j] ^ flip) & H;          // 0x80 per negative float
            unsigned nm = (t1 >> 7) * 0xFFu;           // 0xFF per negative
            unsigned q01 = __byte_perm(__float_as_uint(f[4*j+0]),
                                       __float_as_uint(f[4*j+1]), 0x0062);
            unsigned q23 = __byte_perm(__float_as_uint(f[4*j+2]),
                                       __float_as_uint(f[4*j+3]), 0x0062);
            unsigned qraw = __byte_perm(q01, q23, 0x5410);
            p[j]  = qraw ^ nm ^ flip;                  // overwrite: level-2 plane
            pm[j] = p[j] & NH;
        }
        int d2 = search_plane(p, pm, msk, r, m);
        cur |= (unsigned)d2 << 16;
        refine_mask(msk, p, pm, d2);

        if (m > 1) {
            // ---- rare: top-16-bit collision. Convert f->ordered in place,
            //      run byte levels 3 and 4 over reused p/pm. ----
            #pragma unroll
            for (int i = 0; i < V4 * 4; i++)
                f[i] = __uint_as_float(f2ord(__float_as_uint(f[i])) ^ flip);

            #pragma unroll
            for (int j = 0; j < V4; j++) {
                unsigned a01 = __byte_perm(__float_as_uint(f[4*j+0]),
                                           __float_as_uint(f[4*j+1]), 0x0051);
                unsigned a23 = __byte_perm(__float_as_uint(f[4*j+2]),
                                           __float_as_uint(f[4*j+3]), 0x0051);
                p[j]  = __byte_perm(a01, a23, 0x5410);   // byte1 plane (ordered)
                pm[j] = p[j] & NH;
            }
            int d3 = search_plane(p, pm, msk, r, m);
            cur |= (unsigned)d3 << 8;
            refine_mask(msk, p, pm, d3);

            #pragma unroll
            for (int j = 0; j < V4; j++) {
                unsigned a01 = __byte_perm(__float_as_uint(f[4*j+0]),
                                           __float_as_uint(f[4*j+1]), 0x0040);
                unsigned a23 = __byte_perm(__float_as_uint(f[4*j+2]),
                                           __float_as_uint(f[4*j+3]), 0x0040);
                p[j]  = __byte_perm(a01, a23, 0x5410);   // byte0 plane (ordered)
                pm[j] = p[j] & NH;
            }
            int d4 = search_plane(p, pm, msk, r, m);
            cur |= (unsigned)d4;
            thr_ord = cur;            // full 32 bits decided (duplicates exact)
            resolved = true;

            // restore f to raw floats
            #pragma unroll
            for (int i = 0; i < V4 * 4; i++)
                f[i] = __uint_as_float(ord2f(__float_as_uint(f[i]) ^ flip));
        }
    }
    if (!resolved) {
        thr_ord = extract_unique(msk, f, flip);   // unique survivor's full value
    }

    // ---- threshold pass in float domain ----
    if (largest) {
        const float thr = __uint_as_float(ord2f(thr_ord));
        #pragma unroll
        for (int i = 0; i < V4; i++) {
            float4 o;
            o.x = (f[4*i+0] >= thr) ? f[4*i+0] : 0.0f;
            o.y = (f[4*i+1] >= thr) ? f[4*i+1] : 0.0f;
            o.z = (f[4*i+2] >= thr) ? f[4*i+2] : 0.0f;
            o.w = (f[4*i+3] >= thr) ? f[4*i+3] : 0.0f;
            xout[lane + 32 * i] = o;
        }
    } else {
        const float thr = __uint_as_float(ord2f(thr_ord ^ flip));
        #pragma unroll
        for (int i = 0; i < V4; i++) {
            float4 o;
            o.x = (f[4*i+0] <= thr) ? f[4*i+0] : 0.0f;
            o.y = (f[4*i+1] <= thr) ? f[4*i+1] : 0.0f;
            o.z = (f[4*i+2] <= thr) ? f[4*i+2] : 0.0f;
            o.w = (f[4*i+3] <= thr) ? f[4*i+3] : 0.0f;
            xout[lane + 32 * i] = o;
        }
    }
}

extern "C" void kernel_launch(void* const* d_in, const int* in_sizes, int n_in,
                              void* d_out, int out_size)
{
    const float* x    = (const float*)d_in[0];
    const int*   kptr = (const int*)d_in[1];
    const int*   lptr = (const int*)d_in[2];
    float* out = (float*)d_out;

    int nrows = in_sizes[0] / C_DIM;
    int blocks = (nrows + WARPS - 1) / WARPS;
    topk_mask_kernel<<<blocks, WARPS * 32>>>(x, kptr, lptr, out, nrows);
}

// round 8
// speedup vs baseline: 1.2362x; 1.0374x over previous
#include <cuda_runtime.h>
#include <cstdint>

// Per-row exact top-k masking (keep k largest/smallest along last axis, zero rest).
// One warp per row of C=768 floats, all data register-resident, NO shared memory.
// Up to four masked byte-plane binary searches find the exact 32-bit threshold;
// level-1 search is specialized mask-free (all bytes active) and msk[] is born
// at the first refine, cutting peak live registers to ~50 so 5 CTAs/SM fit
// under __launch_bounds__(256,5) (48-reg cap).

#define FULL_MASK 0xFFFFFFFFu

constexpr int C_DIM = 768;
constexpr int V4    = 6;     // float4 loads per lane (24 values/lane)
constexpr int WARPS = 8;     // rows per block

__device__ __forceinline__ unsigned f2ord(unsigned b) {
    return b ^ (unsigned)(((int)b >> 31) | 0x80000000);
}
__device__ __forceinline__ unsigned ord2f(unsigned u) {
    return u ^ (unsigned)(0x80000000u | ~((unsigned)((int)u >> 31)));
}

// Level-1 (mask-free) byte search: all 768 bytes active.
__device__ __forceinline__ int search_plane_l1(const unsigned* pl, const unsigned* plm,
                                               int& r, int& m)
{
    const unsigned REP1 = 0x01010101u;
    const unsigned H    = 0x80808080u;
    unsigned acc = 0;
    #pragma unroll
    for (int j = 0; j < V4; j++) acc = __dp4a(pl[j] & H, REP1, acc);
    const int n1 = (int)(__reduce_add_sync(FULL_MASK, acc) >> 7);

    int lo = 0, hi = 128, flo, fhi, base;
    if (n1 >= r) {   // threshold byte has bit7 set
        base = 128; flo = n1; fhi = 0;
        #pragma unroll 1
        for (int it = 0; it < 7; it++) {
            int mid = (lo + hi) >> 1;
            unsigned crep = (unsigned)(128 - mid) * REP1;
            unsigned a2 = 0;
            #pragma unroll
            for (int j = 0; j < V4; j++) {
                unsigned s = plm[j] + crep;           // bit7 <=> low7 >= mid
                a2 = __dp4a(s & pl[j] & H, REP1, a2);
            }
            int cnt = (int)(__reduce_add_sync(FULL_MASK, a2) >> 7);
            if (cnt >= r) { lo = mid; flo = cnt; } else { hi = mid; fhi = cnt; }
        }
    } else {         // threshold byte has bit7 clear
        base = 0; flo = m; fhi = n1;
        #pragma unroll 1
        for (int it = 0; it < 7; it++) {
            int mid = (lo + hi) >> 1;
            unsigned crep = (unsigned)(128 - mid) * REP1;
            unsigned a2 = 0;
            #pragma unroll
            for (int j = 0; j < V4; j++) {
                unsigned s = plm[j] + crep;
                a2 = __dp4a((s | pl[j]) & H, REP1, a2);
            }
            int cnt = (int)(__reduce_add_sync(FULL_MASK, a2) >> 7);
            if (cnt >= r) { lo = mid; flo = cnt; } else { hi = mid; fhi = cnt; }
        }
    }
    r -= fhi;
    m  = flo - fhi;
    return base + lo;
}

// Masked byte search (levels >= 2). msk: 0x80 per active byte.
__device__ __forceinline__ int search_plane(const unsigned* pl, const unsigned* plm,
                                            const unsigned* msk, int& r, int& m)
{
    const unsigned REP1 = 0x01010101u;
    unsigned acc = 0;
    #pragma unroll
    for (int j = 0; j < V4; j++) acc = __dp4a(pl[j] & msk[j], REP1, acc);
    const int n1 = (int)(__reduce_add_sync(FULL_MASK, acc) >> 7);

    int lo = 0, hi = 128, flo, fhi, base;
    if (n1 >= r) {
        base = 128; flo = n1; fhi = 0;
        #pragma unroll 1
        for (int it = 0; it < 7; it++) {
            int mid = (lo + hi) >> 1;
            unsigned crep = (unsigned)(128 - mid) * REP1;
            unsigned a2 = 0;
            #pragma unroll
            for (int j = 0; j < V4; j++) {
                unsigned s = plm[j] + crep;
                a2 = __dp4a(s & pl[j] & msk[j], REP1, a2);
            }
            int cnt = (int)(__reduce_add_sync(FULL_MASK, a2) >> 7);
            if (cnt >= r) { lo = mid; flo = cnt; } else { hi = mid; fhi = cnt; }
        }
    } else {
        base = 0; flo = m; fhi = n1;
        #pragma unroll 1
        for (int it = 0; it < 7; it++) {
            int mid = (lo + hi) >> 1;
            unsigned crep = (unsigned)(128 - mid) * REP1;
            unsigned a2 = 0;
            #pragma unroll
            for (int j = 0; j < V4; j++) {
                unsigned s = plm[j] + crep;
                a2 = __dp4a((s | pl[j]) & msk[j], REP1, a2);
            }
            int cnt = (int)(__reduce_add_sync(FULL_MASK, a2) >> 7);
            if (cnt >= r) { lo = mid; flo = cnt; } else { hi = mid; fhi = cnt; }
        }
    }
    r -= fhi;
    m  = flo - fhi;
    return base + lo;
}

// First refine: msk is BORN here as the byte-equality mask (no prior msk).
__device__ __forceinline__ void refine_mask_init(unsigned* msk, const unsigned* pl,
                                                 const unsigned* plm, int d)
{
    const unsigned NH = 0x7F7F7F7Fu;
    const unsigned H  = 0x80808080u;
    const unsigned drep = (unsigned)d * 0x01010101u;
    const unsigned dr7  = drep & NH;
    #pragma unroll
    for (int j = 0; j < V4; j++) {
        unsigned z = pl[j] ^ drep;
        unsigned a = (plm[j] ^ dr7) + NH;
        msk[j] = ~a & ~z & H;                    // one LOP3
    }
}

// Subsequent refines: intersect with existing msk.
__device__ __forceinline__ void refine_mask(unsigned* msk, const unsigned* pl,
                                            const unsigned* plm, int d)
{
    const unsigned NH = 0x7F7F7F7Fu;
    const unsigned drep = (unsigned)d * 0x01010101u;
    const unsigned dr7  = drep & NH;
    #pragma unroll
    for (int j = 0; j < V4; j++) {
        unsigned z = pl[j] ^ drep;
        unsigned a = (plm[j] ^ dr7) + NH;
        msk[j] = ~a & ~z & msk[j];               // one LOP3 (msk is 0x80-only)
    }
}

// Exactly one active byte remains: return its full ordered value (warp-wide).
__device__ __forceinline__ unsigned extract_unique(const unsigned* msk,
                                                   const float* f, unsigned flip)
{
    unsigned best = 0;
    #pragma unroll
    for (int j = 0; j < V4; j++) {
        unsigned y = msk[j];
        if (y) {
            #pragma unroll
            for (int b = 0; b < 4; b++)
                if (y & (0x80u << (8*b)))
                    best = f2ord(__float_as_uint(f[4*j+b])) ^ flip;
        }
    }
    return __reduce_max_sync(FULL_MASK, best);
}

__global__ __launch_bounds__(WARPS * 32, 5)
void topk_mask_kernel(const float* __restrict__ x,
                      const int* __restrict__ kptr,
                      const int* __restrict__ lptr,
                      float* __restrict__ out,
                      int nrows)
{
    const int warp = threadIdx.x >> 5;
    const int lane = threadIdx.x & 31;
    const int row  = blockIdx.x * WARPS + warp;
    if (row >= nrows) return;

    const int k       = *kptr;
    const int largest = *lptr;
    const unsigned flip = largest ? 0u : 0xFFFFFFFFu;

    const float4* __restrict__ xin =
        reinterpret_cast<const float4*>(x + (size_t)row * C_DIM);
    float4* __restrict__ xout =
        reinterpret_cast<float4*>(out + (size_t)row * C_DIM);

    const unsigned H  = 0x80808080u;
    const unsigned NH = 0x7F7F7F7Fu;
    const unsigned HX = H ^ flip;

    // ---- load x; pack ordered top-byte plane into p/pm ----
    float f[V4 * 4];
    unsigned p[V4], pm[V4], msk[V4];
    #pragma unroll
    for (int j = 0; j < V4; j++) {
        float4 v = xin[lane + 32 * j];
        f[4*j+0] = v.x; f[4*j+1] = v.y; f[4*j+2] = v.z; f[4*j+3] = v.w;
        unsigned p01 = __byte_perm(__float_as_uint(v.x), __float_as_uint(v.y), 0x0073);
        unsigned p23 = __byte_perm(__float_as_uint(v.z), __float_as_uint(v.w), 0x0073);
        unsigned pk  = __byte_perm(p01, p23, 0x5410);
        unsigned s   = pk & H;
        unsigned mm  = (s >> 7) * 0x7Fu;   // ordered-byte transform for negatives
        p[j]  = pk ^ mm ^ HX;
        pm[j] = p[j] & NH;
    }

    // ---- level 1: top byte (mask-free) ----
    int r = k, m = C_DIM;
    int d = search_plane_l1(p, pm, r, m);
    unsigned cur = (unsigned)d << 24;
    refine_mask_init(msk, p, pm, d);

    unsigned thr_ord;
    bool resolved = false;

    if (m > 1) {
        // ---- level 2 plane (byte 2, ordered) built IN PLACE over p/pm ----
        #pragma unroll
        for (int j = 0; j < V4; j++) {
            unsigned t1 = ~(p[j] ^ flip) & H;          // 0x80 per negative float
            unsigned nm = (t1 >> 7) * 0xFFu;           // 0xFF per negative
            unsigned q01 = __byte_perm(__float_as_uint(f[4*j+0]),
                                       __float_as_uint(f[4*j+1]), 0x0062);
            unsigned q23 = __byte_perm(__float_as_uint(f[4*j+2]),
                                       __float_as_uint(f[4*j+3]), 0x0062);
            unsigned qraw = __byte_perm(q01, q23, 0x5410);
            p[j]  = qraw ^ nm ^ flip;                  // overwrite: level-2 plane
            pm[j] = p[j] & NH;
        }
        int d2 = search_plane(p, pm, msk, r, m);
        cur |= (unsigned)d2 << 16;
        refine_mask(msk, p, pm, d2);

        if (m > 1) {
            // ---- rare: top-16-bit collision. Convert f->ordered in place,
            //      run byte levels 3 and 4 over reused p/pm. ----
            #pragma unroll
            for (int i = 0; i < V4 * 4; i++)
                f[i] = __uint_as_float(f2ord(__float_as_uint(f[i])) ^ flip);

            #pragma unroll
            for (int j = 0; j < V4; j++) {
                unsigned a01 = __byte_perm(__float_as_uint(f[4*j+0]),
                                           __float_as_uint(f[4*j+1]), 0x0051);
                unsigned a23 = __byte_perm(__float_as_uint(f[4*j+2]),
                                           __float_as_uint(f[4*j+3]), 0x0051);
                p[j]  = __byte_perm(a01, a23, 0x5410);   // byte1 plane (ordered)
                pm[j] = p[j] & NH;
            }
            int d3 = search_plane(p, pm, msk, r, m);
            cur |= (unsigned)d3 << 8;
            refine_mask(msk, p, pm, d3);

            #pragma unroll
            for (int j = 0; j < V4; j++) {
                unsigned a01 = __byte_perm(__float_as_uint(f[4*j+0]),
                                           __float_as_uint(f[4*j+1]), 0x0040);
                unsigned a23 = __byte_perm(__float_as_uint(f[4*j+2]),
                                           __float_as_uint(f[4*j+3]), 0x0040);
                p[j]  = __byte_perm(a01, a23, 0x5410);   // byte0 plane (ordered)
                pm[j] = p[j] & NH;
            }
            int d4 = search_plane(p, pm, msk, r, m);
            cur |= (unsigned)d4;
            thr_ord = cur;            // full 32 bits decided (duplicates exact)
            resolved = true;

            // restore f to raw floats
            #pragma unroll
            for (int i = 0; i < V4 * 4; i++)
                f[i] = __uint_as_float(ord2f(__float_as_uint(f[i]) ^ flip));
        }
    }
    if (!resolved) {
        thr_ord = extract_unique(msk, f, flip);   // unique survivor's full value
    }

    // ---- threshold pass in float domain ----
    if (largest) {
        const float thr = __uint_as_float(ord2f(thr_ord));
        #pragma unroll
        for (int i = 0; i < V4; i++) {
            float4 o;
            o.x = (f[4*i+0] >= thr) ? f[4*i+0] : 0.0f;
            o.y = (f[4*i+1] >= thr) ? f[4*i+1] : 0.0f;
            o.z = (f[4*i+2] >= thr) ? f[4*i+2] : 0.0f;
            o.w = (f[4*i+3] >= thr) ? f[4*i+3] : 0.0f;
            xout[lane + 32 * i] = o;
        }
    } else {
        const float thr = __uint_as_float(ord2f(thr_ord ^ flip));
        #pragma unroll
        for (int i = 0; i < V4; i++) {
            float4 o;
            o.x = (f[4*i+0] <= thr) ? f[4*i+0] : 0.0f;
            o.y = (f[4*i+1] <= thr) ? f[4*i+1] : 0.0f;
            o.z = (f[4*i+2] <= thr) ? f[4*i+2] : 0.0f;
            o.w = (f[4*i+3] <= thr) ? f[4*i+3] : 0.0f;
            xout[lane + 32 * i] = o;
        }
    }
}

extern "C" void kernel_launch(void* const* d_in, const int* in_sizes, int n_in,
                              void* d_out, int out_size)
{
    const float* x    = (const float*)d_in[0];
    const int*   kptr = (const int*)d_in[1];
    const int*   lptr = (const int*)d_in[2];
    float* out = (float*)d_out;

    int nrows = in_sizes[0] / C_DIM;
    int blocks = (nrows + WARPS - 1) / WARPS;
    topk_mask_kernel<<<blocks, WARPS * 32>>>(x, kptr, lptr, out, nrows);
}